// round 17
// baseline (speedup 1.0000x reference)
#include <cuda_runtime.h>
#include <cuda_bf16.h>
#include <math.h>
#include <stdint.h>

#define BB 8
#define NN 2048
#define DD 384
#define CP 64
#define NF 10

__device__ float g_M [CP * CP];
__device__ __nv_bfloat16 g_Wvh[DD * CP];
__device__ __nv_bfloat16 g_Wvl[DD * CP];
__device__ __nv_bfloat16 g_An_hi[BB * NN * CP];
__device__ __nv_bfloat16 g_An_lo[BB * NN * CP];
__device__ __nv_bfloat16 g_U_hi [BB * NN * CP];
__device__ __nv_bfloat16 g_U_lo [BB * NN * CP];
__device__ __nv_bfloat16 g_Bk_hi[BB * CP * NN];
__device__ __nv_bfloat16 g_Bk_lo[BB * CP * NN];
__device__ __nv_bfloat16 g_Zh[BB * NN * CP];
__device__ __nv_bfloat16 g_Zl[BB * NN * CP];
// split-KV partials (raw, unnormalized)
__device__ float g_Pz[2 * BB * NN * CP];
__device__ float g_Pm[2 * BB * NN];
__device__ float g_Pl[2 * BB * NN];

typedef unsigned long long ull;

__device__ __forceinline__ uint32_t smem_u32(const void* p) {
    uint32_t a;
    asm("{ .reg .u64 t; cvta.to.shared.u64 t, %1; cvt.u32.u64 %0, t; }" : "=r"(a) : "l"(p));
    return a;
}
__device__ __forceinline__ void cp16(uint32_t dst, const void* src) {
    asm volatile("cp.async.cg.shared.global [%0], [%1], 16;" :: "r"(dst), "l"(src));
}
#define CP_COMMIT() asm volatile("cp.async.commit_group;" ::: "memory")
#define CP_WAIT0()  asm volatile("cp.async.wait_group 0;" ::: "memory")

__device__ __forceinline__ uint32_t cvt2(float hi, float lo) {
    uint32_t r; asm("cvt.rn.bf16x2.f32 %0, %1, %2;" : "=r"(r) : "f"(hi), "f"(lo)); return r;
}
__device__ __forceinline__ ull pk2(float lo, float hi) {
    ull d; asm("mov.b64 %0, {%1, %2};" : "=l"(d) : "f"(lo), "f"(hi)); return d;
}
__device__ __forceinline__ void upk2(ull v, float& lo, float& hi) {
    asm("mov.b64 {%0, %1}, %2;" : "=f"(lo), "=f"(hi) : "l"(v));
}
__device__ __forceinline__ ull fma2(ull a, ull b, ull c) {
    ull d; asm("fma.rn.f32x2 %0, %1, %2, %3;" : "=l"(d) : "l"(a), "l"(b), "l"(c)); return d;
}
__device__ __forceinline__ void mma16816(float* d, const uint32_t* a, const uint32_t* b) {
    asm volatile("mma.sync.aligned.m16n8k16.row.col.f32.bf16.bf16.f32 "
        "{%0,%1,%2,%3}, {%4,%5,%6,%7}, {%8,%9}, {%0,%1,%2,%3};"
        : "+f"(d[0]), "+f"(d[1]), "+f"(d[2]), "+f"(d[3])
        : "r"(a[0]), "r"(a[1]), "r"(a[2]), "r"(a[3]), "r"(b[0]), "r"(b[1]));
}

// ---------------- 1. prep: M' (warp per 4x4 tile) + Wv' split ----------------
#define MTBLK 32
#define WBLK ((DD * CP + 255) / 256)
__global__ void __launch_bounds__(256) prep_kernel(
        const float* __restrict__ Wq, const float* __restrict__ bq,
        const float* __restrict__ Wk, const float* __restrict__ bk,
        const float* __restrict__ Wv, const float* __restrict__ bv) {
    int t = threadIdx.x;
    if (blockIdx.x < MTBLK) {
        int w = blockIdx.x * 8 + (t >> 5);
        int wi = w >> 4, wj = w & 15;
        int l = t & 31;
        float acc[4][4];
#pragma unroll
        for (int x = 0; x < 4; x++)
#pragma unroll
            for (int y = 0; y < 4; y++) acc[x][y] = 0.0f;
#pragma unroll
        for (int it = 0; it < 12; it++) {
            int d = l + it * 32;
            float aq[4], ak[4];
#pragma unroll
            for (int x = 0; x < 4; x++) {
                int i = wi * 4 + x;
                aq[x] = (i < 60) ? Wq[d * 60 + i] : ((i == 60) ? bq[d] : 0.0f);
                int j = wj * 4 + x;
                ak[x] = (j < 60) ? Wk[d * 60 + j] : ((j == 60) ? bk[d] : 0.0f);
            }
#pragma unroll
            for (int x = 0; x < 4; x++)
#pragma unroll
                for (int y = 0; y < 4; y++) acc[x][y] = fmaf(aq[x], ak[y], acc[x][y]);
        }
        float scale = sqrtf((float)DD);
#pragma unroll
        for (int x = 0; x < 4; x++)
#pragma unroll
            for (int y = 0; y < 4; y++) {
                float v = acc[x][y];
#pragma unroll
                for (int s = 16; s > 0; s >>= 1) v += __shfl_xor_sync(0xffffffffu, v, s);
                if (l == 0) g_M[(wi * 4 + x) * CP + wj * 4 + y] = v * scale;
            }
    } else {
        int r = (blockIdx.x - MTBLK) * 256 + t;
        if (r < DD * CP) {
            int d = r / CP, c = r % CP;
            float v = (c < 60) ? Wv[d * 60 + c] : ((c == 60) ? bv[d] : 0.0f);
            __nv_bfloat16 h = __float2bfloat16(v);
            g_Wvh[r] = h;
            g_Wvl[r] = __float2bfloat16(v - __bfloat162float(h));
        }
    }
}

// ---------------- 2. fused pe + splits + u-GEMM ----------------
#define BSP 132
__global__ void __launch_bounds__(256) pe_u_kernel(const float* __restrict__ pos) {
    __shared__ float Ms[64][64];
    __shared__ float Bs[64][BSP];
    int b = blockIdx.y, n0 = blockIdx.x * 128, t = threadIdx.x;

#pragma unroll
    for (int j = 0; j < 4; j++) {
        int idx = t + j * 256, row = idx >> 4, c4 = idx & 15;
        *reinterpret_cast<float4*>(&Ms[row][c4 * 4]) =
            *reinterpret_cast<const float4*>(g_M + row * CP + c4 * 4);
    }
    {
        int tok = t >> 1, half = t & 1, n = n0 + tok;
        float x0 = pos[(size_t)b * 3 * NN + n];
        float x1 = pos[(size_t)b * 3 * NN + NN + n];
        float x2 = pos[(size_t)b * 3 * NN + 2 * NN + n];
#pragma unroll
        for (int pp = 0; pp < 15; pp++) {
            int p = 15 * half + pp;
            int coord = p / 10, k = p - coord * 10;
            float x = (coord == 0) ? x0 : ((coord == 1) ? x1 : x2);
            float s, c;
            sincosf(x * (float)(1 << k), &s, &c);
            Bs[coord * 20 + k][tok]      = s;
            Bs[coord * 20 + 10 + k][tok] = c;
        }
        if (half) {
            Bs[60][tok] = 1.0f; Bs[61][tok] = 0.0f;
            Bs[62][tok] = 0.0f; Bs[63][tok] = 0.0f;
        }
    }
    __syncthreads();

    {
        int tk = t & 127, which = t >> 7;
        __nv_bfloat16 tmp[64];
        if (which == 0) {
#pragma unroll
            for (int c = 0; c < 64; c++) tmp[c] = __float2bfloat16(Bs[c][tk]);
        } else {
#pragma unroll
            for (int c = 0; c < 64; c++) {
                float x = Bs[c][tk];
                __nv_bfloat16 h = __float2bfloat16(x);
                tmp[c] = __float2bfloat16(x - __bfloat162float(h));
            }
        }
        float4* d = (float4*)((which ? g_An_lo : g_An_hi) + ((size_t)b * NN + n0 + tk) * CP);
#pragma unroll
        for (int j = 0; j < 8; j++) d[j] = ((float4*)tmp)[j];
    }

#pragma unroll
    for (int j = 0; j < 16; j++) {
        int idx = t + j * 256;
        int ch = idx >> 6, tp = idx & 63;
        float2 v = *reinterpret_cast<float2*>(&Bs[ch][tp * 2]);
        uint32_t hw = cvt2(v.y, v.x);
        float h0 = __uint_as_float(hw << 16);
        float h1 = __uint_as_float(hw & 0xffff0000u);
        uint32_t lw = cvt2(v.y - h1, v.x - h0);
        *reinterpret_cast<uint32_t*>(g_Bk_hi + ((size_t)b * CP + ch) * NN + n0 + tp * 2) = hw;
        *reinterpret_cast<uint32_t*>(g_Bk_lo + ((size_t)b * CP + ch) * NN + n0 + tp * 2) = lw;
    }

    int tx = t & 15, ty = t >> 4;
    ull acc2[4][4];
#pragma unroll
    for (int j = 0; j < 4; j++)
#pragma unroll
        for (int k4 = 0; k4 < 4; k4++) acc2[j][k4] = 0ULL;
#pragma unroll 8
    for (int c = 0; c < 64; c++) {
        float a[4];
#pragma unroll
        for (int j = 0; j < 4; j++) a[j] = Ms[ty * 4 + j][c];
        const ull* bp = reinterpret_cast<const ull*>(&Bs[c][tx * 8]);
        ull b4[4] = { bp[0], bp[1], bp[2], bp[3] };
#pragma unroll
        for (int j = 0; j < 4; j++) {
            ull aj = pk2(a[j], a[j]);
#pragma unroll
            for (int k4 = 0; k4 < 4; k4++) acc2[j][k4] = fma2(aj, b4[k4], acc2[j][k4]);
        }
    }
    float acc[4][8];
#pragma unroll
    for (int j = 0; j < 4; j++)
#pragma unroll
        for (int k4 = 0; k4 < 4; k4++) upk2(acc2[j][k4], acc[j][2 * k4], acc[j][2 * k4 + 1]);
#pragma unroll
    for (int k = 0; k < 8; k++) {
        size_t m = (size_t)b * NN + n0 + tx * 8 + k;
        uint32_t h01 = cvt2(acc[1][k], acc[0][k]);
        uint32_t h23 = cvt2(acc[3][k], acc[2][k]);
        float f0 = __uint_as_float(h01 << 16), f1 = __uint_as_float(h01 & 0xffff0000u);
        float f2 = __uint_as_float(h23 << 16), f3 = __uint_as_float(h23 & 0xffff0000u);
        uint32_t l01 = cvt2(acc[1][k] - f1, acc[0][k] - f0);
        uint32_t l23 = cvt2(acc[3][k] - f3, acc[2][k] - f2);
        *reinterpret_cast<uint2*>(g_U_hi + m * CP + ty * 4) = make_uint2(h01, h23);
        *reinterpret_cast<uint2*>(g_U_lo + m * CP + ty * 4) = make_uint2(l01, l23);
    }
}

// ---------------- 3. split-KV fused flash attention (2 blocks/SM) ----------------
#define PITA 144
#define PITK 272
#define SM_APEH 0
#define SM_APEL 18432
#define SM_STG  36864
#define OFF_UL  18432
#define OFF_KH  36864
#define OFF_KL  54272
#define SM_TOT  (SM_STG + 71680)       // 108544 -> two blocks per SM

__global__ void __launch_bounds__(256, 2) fused_attn_split() {
    extern __shared__ char smc[];
    uint32_t sb = smem_u32(smc);
    const int t = threadIdx.x, w = t >> 5, lane = t & 31;
    const int g = lane >> 2, tg = lane & 3;
    const int b = blockIdx.y, n0 = blockIdx.x * 128;
    const int half = blockIdx.z;
    const int mbase = half * 1024;

    {
        const float4* sh = (const float4*)(g_An_hi + ((size_t)b * NN + n0) * CP);
        const float4* sl = (const float4*)(g_An_lo + ((size_t)b * NN + n0) * CP);
#pragma unroll
        for (int j = 0; j < 4; j++) {
            int li = t + j * 256, row = li >> 3, ch = li & 7;
            *(float4*)(smc + SM_APEH + row * PITA + ch * 16) = sh[li];
            *(float4*)(smc + SM_APEL + row * PITA + ch * 16) = sl[li];
        }
    }

    float zacc[8][4];
#pragma unroll
    for (int cf = 0; cf < 8; cf++)
#pragma unroll
        for (int e = 0; e < 4; e++) zacc[cf][e] = 0.0f;
    float mrun0 = -1e30f, mrun1 = -1e30f, lrun0 = 0.0f, lrun1 = 0.0f;

    for (int mt = 0; mt < 8; mt++) {
        int m0 = mbase + mt * 128;
        {
            uint32_t ub = sb + SM_STG;
#pragma unroll
            for (int j = 0; j < 4; j++) {
                int li = t + j * 256, row = li >> 3, ch = li & 7;
                cp16(ub + row * PITA + ch * 16,
                     g_U_hi + ((size_t)b * NN + m0 + row) * CP + ch * 8);
                cp16(ub + OFF_UL + row * PITA + ch * 16,
                     g_U_lo + ((size_t)b * NN + m0 + row) * CP + ch * 8);
            }
#pragma unroll
            for (int j = 0; j < 4; j++) {
                int li = t + j * 256, row = li >> 4, ch = li & 15;
                cp16(ub + OFF_KH + row * PITK + ch * 16,
                     g_Bk_hi + (size_t)(b * CP + row) * NN + m0 + ch * 8);
                cp16(ub + OFF_KL + row * PITK + ch * 16,
                     g_Bk_lo + (size_t)(b * CP + row) * NN + m0 + ch * 8);
            }
        }
        CP_COMMIT();
        CP_WAIT0();
        __syncthreads();

        const char* UB = smc + SM_STG;

#pragma unroll
        for (int c = 0; c < 2; c++) {
            // ---- S chunk ----
            float sfr[8][4];
#pragma unroll
            for (int mf = 0; mf < 8; mf++)
#pragma unroll
                for (int e = 0; e < 4; e++) sfr[mf][e] = 0.0f;
#pragma unroll
            for (int ks = 0; ks < 4; ks++) {
                uint32_t abase = (uint32_t)((w * 16 + g) * PITA + (ks * 16 + tg * 2) * 2);
                uint32_t ah[4], al_[4];
                ah[0]  = *(const uint32_t*)(smc + SM_APEH + abase);
                ah[1]  = *(const uint32_t*)(smc + SM_APEH + abase + 8 * PITA);
                ah[2]  = *(const uint32_t*)(smc + SM_APEH + abase + 16);
                ah[3]  = *(const uint32_t*)(smc + SM_APEH + abase + 8 * PITA + 16);
                al_[0] = *(const uint32_t*)(smc + SM_APEL + abase);
                al_[1] = *(const uint32_t*)(smc + SM_APEL + abase + 8 * PITA);
                al_[2] = *(const uint32_t*)(smc + SM_APEL + abase + 16);
                al_[3] = *(const uint32_t*)(smc + SM_APEL + abase + 8 * PITA + 16);
#pragma unroll
                for (int mf = 0; mf < 8; mf++) {
                    uint32_t bbase = (uint32_t)(((c * 8 + mf) * 8 + g) * PITA + (ks * 16 + tg * 2) * 2);
                    uint32_t bh[2] = { *(const uint32_t*)(UB + bbase),
                                       *(const uint32_t*)(UB + bbase + 16) };
                    uint32_t bl[2] = { *(const uint32_t*)(UB + OFF_UL + bbase),
                                       *(const uint32_t*)(UB + OFF_UL + bbase + 16) };
                    mma16816(sfr[mf], ah, bh);
                    mma16816(sfr[mf], ah, bl);
                    mma16816(sfr[mf], al_, bh);
                }
            }

            // ---- online softmax on chunk ----
            float tm0 = -1e30f, tm1 = -1e30f;
#pragma unroll
            for (int mf = 0; mf < 8; mf++) {
                tm0 = fmaxf(tm0, fmaxf(sfr[mf][0], sfr[mf][1]));
                tm1 = fmaxf(tm1, fmaxf(sfr[mf][2], sfr[mf][3]));
            }
            tm0 = fmaxf(tm0, __shfl_xor_sync(0xffffffffu, tm0, 1));
            tm0 = fmaxf(tm0, __shfl_xor_sync(0xffffffffu, tm0, 2));
            tm1 = fmaxf(tm1, __shfl_xor_sync(0xffffffffu, tm1, 1));
            tm1 = fmaxf(tm1, __shfl_xor_sync(0xffffffffu, tm1, 2));
            float nm0 = fmaxf(mrun0, tm0), nm1 = fmaxf(mrun1, tm1);
            float al0 = __expf(mrun0 - nm0), al1 = __expf(mrun1 - nm1);
            mrun0 = nm0; mrun1 = nm1;
#pragma unroll
            for (int cf = 0; cf < 8; cf++) {
                zacc[cf][0] *= al0; zacc[cf][1] *= al0;
                zacc[cf][2] *= al1; zacc[cf][3] *= al1;
            }
            float rs0 = 0.0f, rs1 = 0.0f;
            uint32_t ph[8][2], pl[8][2];
#pragma unroll
            for (int mf = 0; mf < 8; mf++) {
                float p0 = __expf(sfr[mf][0] - nm0), p1 = __expf(sfr[mf][1] - nm0);
                float p2 = __expf(sfr[mf][2] - nm1), p3 = __expf(sfr[mf][3] - nm1);
                rs0 += p0 + p1; rs1 += p2 + p3;
                uint32_t h01 = cvt2(p1, p0);
                uint32_t h23 = cvt2(p3, p2);
                ph[mf][0] = h01; ph[mf][1] = h23;
                float f0 = __uint_as_float(h01 << 16), f1 = __uint_as_float(h01 & 0xffff0000u);
                float f2 = __uint_as_float(h23 << 16), f3 = __uint_as_float(h23 & 0xffff0000u);
                pl[mf][0] = cvt2(p1 - f1, p0 - f0);
                pl[mf][1] = cvt2(p3 - f3, p2 - f2);
            }
            rs0 += __shfl_xor_sync(0xffffffffu, rs0, 1);
            rs0 += __shfl_xor_sync(0xffffffffu, rs0, 2);
            rs1 += __shfl_xor_sync(0xffffffffu, rs1, 1);
            rs1 += __shfl_xor_sync(0xffffffffu, rs1, 2);
            lrun0 = lrun0 * al0 + rs0;
            lrun1 = lrun1 * al1 + rs1;

            // ---- Z chunk ----
#pragma unroll
            for (int ks = 0; ks < 4; ks++) {
                uint32_t aph[4] = { ph[2 * ks][0], ph[2 * ks][1], ph[2 * ks + 1][0], ph[2 * ks + 1][1] };
                uint32_t apl[4] = { pl[2 * ks][0], pl[2 * ks][1], pl[2 * ks + 1][0], pl[2 * ks + 1][1] };
#pragma unroll
                for (int cf = 0; cf < 8; cf++) {
                    uint32_t bb = (uint32_t)((cf * 8 + g) * PITK + ((c * 4 + ks) * 16 + tg * 2) * 2);
                    uint32_t kh[2] = { *(const uint32_t*)(UB + OFF_KH + bb),
                                       *(const uint32_t*)(UB + OFF_KH + bb + 16) };
                    uint32_t kl[2] = { *(const uint32_t*)(UB + OFF_KL + bb),
                                       *(const uint32_t*)(UB + OFF_KL + bb + 16) };
                    mma16816(zacc[cf], aph, kh);
                    mma16816(zacc[cf], apl, kh);
                    mma16816(zacc[cf], aph, kl);
                }
            }
        }
        __syncthreads();
    }

    // ---- epilogue: write raw partials (zacc, m, l) ----
    int nl0 = n0 + w * 16 + g, nl1 = nl0 + 8;
    size_t base = (size_t)(half * BB + b) * NN;
    float* Z0 = g_Pz + (base + nl0) * CP;
    float* Z1 = g_Pz + (base + nl1) * CP;
#pragma unroll
    for (int cf = 0; cf < 8; cf++) {
        int c0 = cf * 8 + tg * 2;
        *reinterpret_cast<float2*>(Z0 + c0) = make_float2(zacc[cf][0], zacc[cf][1]);
        *reinterpret_cast<float2*>(Z1 + c0) = make_float2(zacc[cf][2], zacc[cf][3]);
    }
    if (tg == 0) {
        g_Pm[base + nl0] = mrun0;
        g_Pm[base + nl1] = mrun1;
        g_Pl[base + nl0] = lrun0;
        g_Pl[base + nl1] = lrun1;
    }
}

// ---------------- 3b. combine the two key-halves -> bf16-split Z ----------------
__global__ void __launch_bounds__(256) combine_kernel() {
    __shared__ float a0s[128], a1s[128];
    int b = blockIdx.y, n0 = blockIdx.x * 128, t = threadIdx.x;
    if (t < 128) {
        size_t i0 = (size_t)b * NN + n0 + t;
        size_t i1 = (size_t)(BB + b) * NN + n0 + t;
        float m0 = g_Pm[i0], m1 = g_Pm[i1];
        float l0 = g_Pl[i0], l1 = g_Pl[i1];
        float M = fmaxf(m0, m1);
        float e0 = __expf(m0 - M), e1 = __expf(m1 - M);
        float inv = 1.0f / (e0 * l0 + e1 * l1);
        a0s[t] = e0 * inv;
        a1s[t] = e1 * inv;
    }
    __syncthreads();
#pragma unroll
    for (int j = 0; j < 16; j++) {
        int idx = t + j * 256;
        int nn = idx >> 5, cp2 = (idx & 31) * 2;
        int n = n0 + nn;
        const float2 z0 = *reinterpret_cast<const float2*>(
            g_Pz + ((size_t)b * NN + n) * CP + cp2);
        const float2 z1 = *reinterpret_cast<const float2*>(
            g_Pz + ((size_t)(BB + b) * NN + n) * CP + cp2);
        float a0 = a0s[nn], a1 = a1s[nn];
        float v0 = a0 * z0.x + a1 * z1.x;
        float v1 = a0 * z0.y + a1 * z1.y;
        uint32_t h = cvt2(v1, v0);
        float f0 = __uint_as_float(h << 16), f1 = __uint_as_float(h & 0xffff0000u);
        uint32_t l = cvt2(v1 - f1, v0 - f0);
        *reinterpret_cast<uint32_t*>(g_Zh + ((size_t)b * NN + n) * CP + cp2) = h;
        *reinterpret_cast<uint32_t*>(g_Zl + ((size_t)b * NN + n) * CP + cp2) = l;
    }
}

// ---------------- 4. tensor-core output GEMM ----------------
#define GP_WVH 0
#define GP_WVL 18432
#define GP_ZH  36864
#define GP_ZL  55296
#define GP_TOT 73728

__global__ void __launch_bounds__(256, 2) gemm_out_tc(float* __restrict__ Out) {
    extern __shared__ char sm2[];
    int b = blockIdx.z, d0 = blockIdx.y * 128, n0 = blockIdx.x * 128;
    int t = threadIdx.x, w = t >> 5, lane = t & 31;
    int g = lane >> 2, tg = lane & 3;

#pragma unroll
    for (int j = 0; j < 4; j++) {
        int li = t + j * 256, row = li >> 3, ch = li & 7;
        *(float4*)(sm2 + GP_WVH + row * PITA + ch * 16) =
            *(const float4*)(g_Wvh + (size_t)(d0 + row) * CP + ch * 8);
        *(float4*)(sm2 + GP_WVL + row * PITA + ch * 16) =
            *(const float4*)(g_Wvl + (size_t)(d0 + row) * CP + ch * 8);
        *(float4*)(sm2 + GP_ZH + row * PITA + ch * 16) =
            *(const float4*)(g_Zh + ((size_t)b * NN + n0 + row) * CP + ch * 8);
        *(float4*)(sm2 + GP_ZL + row * PITA + ch * 16) =
            *(const float4*)(g_Zl + ((size_t)b * NN + n0 + row) * CP + ch * 8);
    }
    __syncthreads();

    float acc[16][4];
#pragma unroll
    for (int nf = 0; nf < 16; nf++)
#pragma unroll
        for (int e = 0; e < 4; e++) acc[nf][e] = 0.0f;

#pragma unroll
    for (int ks = 0; ks < 4; ks++) {
        uint32_t abase = (uint32_t)((w * 16 + g) * PITA + (ks * 16 + tg * 2) * 2);
        uint32_t ah[4], al_[4];
        ah[0]  = *(const uint32_t*)(sm2 + GP_WVH + abase);
        ah[1]  = *(const uint32_t*)(sm2 + GP_WVH + abase + 8 * PITA);
        ah[2]  = *(const uint32_t*)(sm2 + GP_WVH + abase + 16);
        ah[3]  = *(const uint32_t*)(sm2 + GP_WVH + abase + 8 * PITA + 16);
        al_[0] = *(const uint32_t*)(sm2 + GP_WVL + abase);
        al_[1] = *(const uint32_t*)(sm2 + GP_WVL + abase + 8 * PITA);
        al_[2] = *(const uint32_t*)(sm2 + GP_WVL + abase + 16);
        al_[3] = *(const uint32_t*)(sm2 + GP_WVL + abase + 8 * PITA + 16);
#pragma unroll
        for (int nf = 0; nf < 16; nf++) {
            uint32_t bbase = (uint32_t)((nf * 8 + g) * PITA + (ks * 16 + tg * 2) * 2);
            uint32_t bh[2] = { *(const uint32_t*)(sm2 + GP_ZH + bbase),
                               *(const uint32_t*)(sm2 + GP_ZH + bbase + 16) };
            uint32_t bl[2] = { *(const uint32_t*)(sm2 + GP_ZL + bbase),
                               *(const uint32_t*)(sm2 + GP_ZL + bbase + 16) };
            mma16816(acc[nf], ah, bh);
            mma16816(acc[nf], ah, bl);
            mma16816(acc[nf], al_, bh);
        }
    }

    float* Op = Out + (size_t)b * DD * NN;
    int dd0 = d0 + w * 16 + g, dd1 = dd0 + 8;
#pragma unroll
    for (int nf = 0; nf < 16; nf++) {
        int n = n0 + nf * 8 + tg * 2;
        *reinterpret_cast<float2*>(Op + (size_t)dd0 * NN + n) = make_float2(acc[nf][0], acc[nf][1]);
        *reinterpret_cast<float2*>(Op + (size_t)dd1 * NN + n) = make_float2(acc[nf][2], acc[nf][3]);
    }
}

// ---------------------------------------------------------------------------
extern "C" void kernel_launch(void* const* d_in, const int* in_sizes, int n_in,
                              void* d_out, int out_size) {
    const float* pos = (const float*)d_in[0];
    const float* Wq  = (const float*)d_in[1];
    const float* bq  = (const float*)d_in[2];
    const float* Wk  = (const float*)d_in[3];
    const float* bk  = (const float*)d_in[4];
    const float* Wv  = (const float*)d_in[5];
    const float* bv  = (const float*)d_in[6];
    float* out = (float*)d_out;

    prep_kernel<<<MTBLK + WBLK, 256>>>(Wq, bq, Wk, bk, Wv, bv);
    pe_u_kernel<<<dim3(NN / 128, BB), 256>>>(pos);

    cudaFuncSetAttribute(fused_attn_split, cudaFuncAttributeMaxDynamicSharedMemorySize, SM_TOT);
    fused_attn_split<<<dim3(NN / 128, BB, 2), 256, SM_TOT>>>();

    combine_kernel<<<dim3(NN / 128, BB), 256>>>();

    cudaFuncSetAttribute(gemm_out_tc, cudaFuncAttributeMaxDynamicSharedMemorySize, GP_TOT);
    gemm_out_tc<<<dim3(NN / 128, DD / 128, BB), 256, GP_TOT>>>(out);
}